// round 9
// baseline (speedup 1.0000x reference)
#include <cuda_runtime.h>
#include <cuda_bf16.h>
#include <math.h>
#include <cstdint>

#define NN 50000
#define NE 800000
#define INF 128
#define HID 256
#define NCLS 64

// ---------------- device scratch ----------------
__device__ int   g_deg[NN];
__device__ int   g_cursor[NN];
__device__ int   g_off[NN + 1];
__device__ int   g_csr[NE];
__device__ float g_invdeg[NN];
__device__ int   g_tsum[64];
// U stored as 4 contiguous chunks u0,u1,u2,u3; chunk c = g_U + c*NN*64
__device__ __align__(16) float g_U[(size_t)4 * NN * 64];
__device__ __align__(16) float g_s[(size_t)2 * NN * 64];   // s2, s1
// g_pre layout: Us=0, Un=16384, Q0=32768, Q1=49152, Q2=65536
__device__ __align__(16) float g_pre[5 * 256 * 64];
__device__ __align__(16) __nv_bfloat16 g_CTh[256 * 128];   // Cbig^T hi [n][k]
__device__ __align__(16) __nv_bfloat16 g_CTl[256 * 128];   // Cbig^T lo
__device__ float g_r[3 * 64];
__device__ float g_e1[NN];
__device__ float g_e2[NN];

// ---------------- CSR build ----------------
__global__ void k_zero_counts() {
    int i = blockIdx.x * blockDim.x + threadIdx.x;
    if (i < NN) { g_deg[i] = 0; g_cursor[i] = 0; }
}

__global__ void k_count(const int* __restrict__ dst) {
    int e = blockIdx.x * blockDim.x + threadIdx.x;
    if (e < NE) atomicAdd(&g_deg[dst[e]], 1);
}

__global__ void k_scan_tiles() {
    __shared__ int sh[1024];
    int t = threadIdx.x;
    int i = blockIdx.x * 1024 + t;
    int v = (i < NN) ? g_deg[i] : 0;
    sh[t] = v;
    __syncthreads();
    for (int d = 1; d < 1024; d <<= 1) {
        int x = 0;
        if (t >= d) x = sh[t - d];
        __syncthreads();
        sh[t] += x;
        __syncthreads();
    }
    if (i < NN) g_off[i] = sh[t] - v;
    if (t == 1023) g_tsum[blockIdx.x] = sh[t];
}

__global__ void k_scan_sums(int ntiles) {
    __shared__ int sh[64];
    int t = threadIdx.x;
    int v = (t < ntiles) ? g_tsum[t] : 0;
    sh[t] = v;
    __syncthreads();
    for (int d = 1; d < 64; d <<= 1) {
        int x = 0;
        if (t >= d) x = sh[t - d];
        __syncthreads();
        sh[t] += x;
        __syncthreads();
    }
    if (t < ntiles) g_tsum[t] = sh[t] - v;
}

__global__ void k_scan_fix() {
    int i = blockIdx.x * blockDim.x + threadIdx.x;
    if (i < NN) {
        g_off[i] += g_tsum[i >> 10];
        int d = g_deg[i];
        g_invdeg[i] = 1.0f / fmaxf((float)d, 1.0f);
        g_e1[i] = (d > 0) ? 1.0f : 0.0f;
    }
    if (i == 0) g_off[NN] = NE;
}

__global__ void k_fill(const int* __restrict__ src, const int* __restrict__ dst) {
    int e = blockIdx.x * blockDim.x + threadIdx.x;
    if (e < NE) {
        int d = dst[e];
        int pos = g_off[d] + atomicAdd(&g_cursor[d], 1);
        g_csr[pos] = src[e];
    }
}

// ---------------- fused precompute stages ----------------
__global__ void k_preA(const float* __restrict__ W2s, const float* __restrict__ W2n,
                       const float* __restrict__ Wfc) {
    int idx = blockIdx.x * blockDim.x + threadIdx.x;
    if (idx >= 2 * 16384) return;
    int which = idx >> 14;
    int j = idx & 16383;
    int r = j >> 6, c = j & 63;
    const float* A = which ? W2n : W2s;
    float acc = 0.f;
    #pragma unroll 8
    for (int k = 0; k < 256; ++k) acc += A[r * 256 + k] * Wfc[k * 64 + c];
    g_pre[which * 16384 + j] = acc;
}

__global__ void k_preB(const float* __restrict__ W1s, const float* __restrict__ W1n) {
    int idx = blockIdx.x * blockDim.x + threadIdx.x;
    if (idx >= 3 * 16384) return;
    int which = idx / 16384;
    int j = idx % 16384;
    int r = j >> 6, c = j & 63;
    const float* Us = g_pre;
    const float* Un = g_pre + 16384;
    float acc = 0.f;
    if (which == 0) {
        #pragma unroll 8
        for (int k = 0; k < 256; ++k) acc += W1s[r * 256 + k] * Us[k * 64 + c];
    } else if (which == 1) {
        #pragma unroll 8
        for (int k = 0; k < 256; ++k)
            acc += W1n[r * 256 + k] * Us[k * 64 + c] + W1s[r * 256 + k] * Un[k * 64 + c];
    } else {
        #pragma unroll 8
        for (int k = 0; k < 256; ++k) acc += W1n[r * 256 + k] * Un[k * 64 + c];
    }
    g_pre[32768 + which * 16384 + j] = acc;
}

__global__ void k_preC(const float* __restrict__ W0s, const float* __restrict__ W0n) {
    int idx = blockIdx.x * blockDim.x + threadIdx.x;
    if (idx >= 4 * 8192) return;
    int chunk = idx >> 13;
    int j = idx & 8191;
    int r = j >> 6, c = j & 63;
    const float* Q0 = g_pre + 32768;
    const float* Q1 = g_pre + 49152;
    const float* Q2 = g_pre + 65536;
    float acc = 0.f;
    if (chunk == 0) {
        #pragma unroll 8
        for (int k = 0; k < 256; ++k) acc += W0s[r * 256 + k] * Q0[k * 64 + c];
    } else if (chunk == 1) {
        #pragma unroll 8
        for (int k = 0; k < 256; ++k)
            acc += W0n[r * 256 + k] * Q0[k * 64 + c] + W0s[r * 256 + k] * Q1[k * 64 + c];
    } else if (chunk == 2) {
        #pragma unroll 8
        for (int k = 0; k < 256; ++k)
            acc += W0n[r * 256 + k] * Q1[k * 64 + c] + W0s[r * 256 + k] * Q2[k * 64 + c];
    } else {
        #pragma unroll 8
        for (int k = 0; k < 256; ++k) acc += W0n[r * 256 + k] * Q2[k * 64 + c];
    }
    __nv_bfloat16 h = __float2bfloat16(acc);
    g_CTh[chunk * 8192 + c * 128 + r] = h;
    g_CTl[chunk * 8192 + c * 128 + r] = __float2bfloat16(acc - __bfloat162float(h));
}

// warp-parallel rvec: one warp per output element (192 outputs)
__global__ void k_rvec(const float* __restrict__ b0, const float* __restrict__ b1,
                       const float* __restrict__ b2, const float* __restrict__ bfc,
                       const float* __restrict__ Wfc) {
    const float* Us = g_pre;
    const float* Un = g_pre + 16384;
    const float* Q0 = g_pre + 32768;
    const float* Q1 = g_pre + 49152;
    const float* Q2 = g_pre + 65536;
    int gw = (blockIdx.x * blockDim.x + threadIdx.x) >> 5;
    int lane = threadIdx.x & 31;
    if (gw >= 192) return;
    int which = gw / 64, c = gw % 64;
    float acc = 0.f;
    if (which == 0) {
        #pragma unroll
        for (int k = lane; k < 256; k += 32)
            acc += b0[k] * Q0[k * 64 + c] + b1[k] * Us[k * 64 + c] + b2[k] * Wfc[k * 64 + c];
    } else if (which == 1) {
        #pragma unroll
        for (int k = lane; k < 256; k += 32)
            acc += b0[k] * Q1[k * 64 + c] + b1[k] * Un[k * 64 + c];
    } else {
        #pragma unroll
        for (int k = lane; k < 256; k += 32)
            acc += b0[k] * Q2[k * 64 + c];
    }
    #pragma unroll
    for (int o = 16; o > 0; o >>= 1)
        acc += __shfl_xor_sync(0xFFFFFFFFu, acc, o);
    if (lane == 0) {
        if (which == 0) acc += bfc[c];
        g_r[gw] = acc;
    }
}

// ---------------- 64-dim mean gather, x8 unrolled, fused add ----------------
// all row strides are 16 float4s. mode: 0 plain ; 1 also g_e2 ; 2 add bias combo
__global__ void k_gather64(const float4* __restrict__ src,
                           const float4* __restrict__ add,
                           float4* __restrict__ out, int mode) {
    int gtid = blockIdx.x * blockDim.x + threadIdx.x;
    int node = gtid >> 4;
    int c = gtid & 15;
    if (node >= NN) return;
    int s = g_off[node], e = g_off[node + 1];
    float4 a0 = make_float4(0.f, 0.f, 0.f, 0.f);
    float4 a1 = make_float4(0.f, 0.f, 0.f, 0.f);
    float4 a2 = make_float4(0.f, 0.f, 0.f, 0.f);
    float4 a3 = make_float4(0.f, 0.f, 0.f, 0.f);
    float ecnt = 0.f;
    int idx = s;
    for (; idx + 8 <= e; idx += 8) {
        int n[8];
        #pragma unroll
        for (int j = 0; j < 8; ++j) n[j] = g_csr[idx + j];
        float4 v[8];
        #pragma unroll
        for (int j = 0; j < 8; ++j) v[j] = src[(size_t)n[j] * 16 + c];
        if (mode == 1 && c == 0) {
            #pragma unroll
            for (int j = 0; j < 8; ++j) ecnt += (g_deg[n[j]] > 0) ? 1.f : 0.f;
        }
        a0.x += v[0].x; a0.y += v[0].y; a0.z += v[0].z; a0.w += v[0].w;
        a1.x += v[1].x; a1.y += v[1].y; a1.z += v[1].z; a1.w += v[1].w;
        a2.x += v[2].x; a2.y += v[2].y; a2.z += v[2].z; a2.w += v[2].w;
        a3.x += v[3].x; a3.y += v[3].y; a3.z += v[3].z; a3.w += v[3].w;
        a0.x += v[4].x; a0.y += v[4].y; a0.z += v[4].z; a0.w += v[4].w;
        a1.x += v[5].x; a1.y += v[5].y; a1.z += v[5].z; a1.w += v[5].w;
        a2.x += v[6].x; a2.y += v[6].y; a2.z += v[6].z; a2.w += v[6].w;
        a3.x += v[7].x; a3.y += v[7].y; a3.z += v[7].z; a3.w += v[7].w;
    }
    for (; idx + 2 <= e; idx += 2) {
        int n0 = g_csr[idx], n1 = g_csr[idx + 1];
        float4 v0 = src[(size_t)n0 * 16 + c];
        float4 v1 = src[(size_t)n1 * 16 + c];
        if (mode == 1 && c == 0)
            ecnt += ((g_deg[n0] > 0) ? 1.f : 0.f) + ((g_deg[n1] > 0) ? 1.f : 0.f);
        a0.x += v0.x; a0.y += v0.y; a0.z += v0.z; a0.w += v0.w;
        a1.x += v1.x; a1.y += v1.y; a1.z += v1.z; a1.w += v1.w;
    }
    if (idx < e) {
        int sn = g_csr[idx];
        float4 v = src[(size_t)sn * 16 + c];
        if (mode == 1 && c == 0) ecnt += (g_deg[sn] > 0) ? 1.f : 0.f;
        a0.x += v.x; a0.y += v.y; a0.z += v.z; a0.w += v.w;
    }
    a0.x += a1.x + a2.x + a3.x;
    a0.y += a1.y + a2.y + a3.y;
    a0.z += a1.z + a2.z + a3.z;
    a0.w += a1.w + a2.w + a3.w;
    float w = g_invdeg[node];
    if (mode == 1 && c == 0) g_e2[node] = ecnt * w;
    float4 r = add[(size_t)node * 16 + c];
    r.x += a0.x * w; r.y += a0.y * w; r.z += a0.z * w; r.w += a0.w * w;
    if (mode == 2) {
        float a = g_e1[node], b = g_e2[node];
        const float4* r0 = (const float4*)g_r;
        const float4* r1 = r0 + 16;
        const float4* r2 = r0 + 32;
        float4 v0 = r0[c], v1 = r1[c], v2 = r2[c];
        r.x += v0.x + a * v1.x + b * v2.x;
        r.y += v0.y + a * v1.y + b * v2.y;
        r.z += v0.z + a * v1.z + b * v2.z;
        r.w += v0.w + a * v1.w + b * v2.w;
    }
    out[(size_t)node * 16 + c] = r;
}

// ---------------- mma.sync bf16 split-precision GEMM ----------------
// BM=64 x BN=128 half-width kernel; colbase selects which 128 output cols.
// Output goes to chunked U: col -> chunk (col>>6), offset (col&63).
#define LDK 136
#define SM_AH 0
#define SM_AL (64 * LDK)
#define SM_BH (2 * 64 * LDK)
#define SM_BL (2 * 64 * LDK + 128 * LDK)
#define SM_HALVES (2 * 64 * LDK + 2 * 128 * LDK)

#define MMA16816(c, a, b0_, b1_) \
    asm volatile("mma.sync.aligned.m16n8k16.row.col.f32.bf16.bf16.f32 " \
        "{%0,%1,%2,%3}, {%4,%5,%6,%7}, {%8,%9}, {%0,%1,%2,%3};" \
        : "+f"((c)[0]), "+f"((c)[1]), "+f"((c)[2]), "+f"((c)[3]) \
        : "r"((a)[0]), "r"((a)[1]), "r"((a)[2]), "r"((a)[3]), \
          "r"(b0_), "r"(b1_))

__global__ __launch_bounds__(256, 2)
void k_wgemm(const float* __restrict__ x, const __nv_bfloat16* __restrict__ CTh,
             const __nv_bfloat16* __restrict__ CTl, float* __restrict__ U,
             int M, int colbase) {
    extern __shared__ __nv_bfloat16 sm[];
    __nv_bfloat16* Ah = sm + SM_AH;
    __nv_bfloat16* Al = sm + SM_AL;
    __nv_bfloat16* Bh = sm + SM_BH;
    __nv_bfloat16* Bl = sm + SM_BL;

    const int tid = threadIdx.x;
    const int bm = blockIdx.x * 64;

    // ---- stage A: 64 rows of x -> bf16 hi/lo (4 threads/row, 32 cols each) ----
    {
        int r = tid >> 2;            // 0..63
        int q = tid & 3;             // 32-col quarter
        int grow = bm + r;
        const float4* xr = (const float4*)(x + (size_t)grow * 128 + q * 32);
        __nv_bfloat16* ah = Ah + r * LDK + q * 32;
        __nv_bfloat16* al = Al + r * LDK + q * 32;
        #pragma unroll
        for (int j = 0; j < 4; ++j) {    // 8 floats per j
            float f[8];
            if (grow < M) {
                float4 v0 = xr[2 * j], v1 = xr[2 * j + 1];
                f[0] = v0.x; f[1] = v0.y; f[2] = v0.z; f[3] = v0.w;
                f[4] = v1.x; f[5] = v1.y; f[6] = v1.z; f[7] = v1.w;
            } else {
                #pragma unroll
                for (int e = 0; e < 8; ++e) f[e] = 0.f;
            }
            uint32_t hp[4], lp[4];
            #pragma unroll
            for (int e = 0; e < 4; ++e) {
                __nv_bfloat16 h0 = __float2bfloat16(f[2 * e]);
                __nv_bfloat16 h1 = __float2bfloat16(f[2 * e + 1]);
                float l0 = f[2 * e]     - __bfloat162float(h0);
                float l1 = f[2 * e + 1] - __bfloat162float(h1);
                __nv_bfloat162 hh = __halves2bfloat162(h0, h1);
                __nv_bfloat162 lv = __halves2bfloat162(__float2bfloat16(l0),
                                                       __float2bfloat16(l1));
                hp[e] = *(uint32_t*)&hh;
                lp[e] = *(uint32_t*)&lv;
            }
            *(uint4*)(ah + 8 * j) = make_uint4(hp[0], hp[1], hp[2], hp[3]);
            *(uint4*)(al + 8 * j) = make_uint4(lp[0], lp[1], lp[2], lp[3]);
        }
    }
    // ---- stage B: 128 CT rows (this half), 2 threads/row ----
    {
        int r = tid >> 1;
        int half = tid & 1;
        const uint4* sh = (const uint4*)(CTh + (size_t)r * 128 + half * 64);
        const uint4* sl = (const uint4*)(CTl + (size_t)r * 128 + half * 64);
        uint4* dh = (uint4*)(Bh + r * LDK + half * 64);
        uint4* dl = (uint4*)(Bl + r * LDK + half * 64);
        #pragma unroll
        for (int j = 0; j < 8; ++j) { dh[j] = sh[j]; dl[j] = sl[j]; }
    }
    __syncthreads();

    const int w = tid >> 5, lane = tid & 31;
    const int wm = (w >> 2) * 32;          // 2 m-groups
    const int wn = (w & 3) * 32;           // 4 n-groups
    const int lr = lane >> 2;
    const int lc = (lane & 3) * 2;

    float acc[2][4][4];
    #pragma unroll
    for (int i = 0; i < 2; ++i)
        #pragma unroll
        for (int j = 0; j < 4; ++j)
            #pragma unroll
            for (int e = 0; e < 4; ++e) acc[i][j][e] = 0.f;

    #pragma unroll
    for (int pass = 0; pass < 3; ++pass) {
        const __nv_bfloat16* As = (pass == 2) ? Al : Ah;
        const __nv_bfloat16* Bs = (pass == 1) ? Bl : Bh;
        #pragma unroll
        for (int ks = 0; ks < 8; ++ks) {
            int kb = ks * 16;
            uint32_t a[2][4];
            #pragma unroll
            for (int fm = 0; fm < 2; ++fm) {
                int r = wm + fm * 16 + lr;
                a[fm][0] = *(const uint32_t*)&As[r * LDK + kb + lc];
                a[fm][1] = *(const uint32_t*)&As[(r + 8) * LDK + kb + lc];
                a[fm][2] = *(const uint32_t*)&As[r * LDK + kb + 8 + lc];
                a[fm][3] = *(const uint32_t*)&As[(r + 8) * LDK + kb + 8 + lc];
            }
            #pragma unroll
            for (int fn = 0; fn < 4; ++fn) {
                int n = wn + fn * 8 + lr;
                uint32_t b0 = *(const uint32_t*)&Bs[n * LDK + kb + lc];
                uint32_t b1 = *(const uint32_t*)&Bs[n * LDK + kb + 8 + lc];
                #pragma unroll
                for (int fm = 0; fm < 2; ++fm)
                    MMA16816(acc[fm][fn], a[fm], b0, b1);
            }
        }
    }

    // ---- epilogue into chunked U ----
    #pragma unroll
    for (int fm = 0; fm < 2; ++fm) {
        int r0 = bm + wm + fm * 16 + lr;
        int r1 = r0 + 8;
        #pragma unroll
        for (int fn = 0; fn < 4; ++fn) {
            int col = colbase + wn + fn * 8 + lc;
            int chunk = col >> 6, off = col & 63;
            float* dst = U + (size_t)chunk * NN * 64 + off;
            if (r0 < M)
                *(float2*)(dst + (size_t)r0 * 64) =
                    make_float2(acc[fm][fn][0], acc[fm][fn][1]);
            if (r1 < M)
                *(float2*)(dst + (size_t)r1 * 64) =
                    make_float2(acc[fm][fn][2], acc[fm][fn][3]);
        }
    }
}

// ---------------- launch ----------------
extern "C" void kernel_launch(void* const* d_in, const int* in_sizes, int n_in,
                              void* d_out, int out_size) {
    const float* x    = (const float*)d_in[0];
    const int*   esrc = (const int*)d_in[1];
    const int*   edst = (const int*)d_in[2];
    const float* W0s  = (const float*)d_in[3];
    const float* W0n  = (const float*)d_in[4];
    const float* b0   = (const float*)d_in[5];
    const float* W1s  = (const float*)d_in[6];
    const float* W1n  = (const float*)d_in[7];
    const float* b1   = (const float*)d_in[8];
    const float* W2s  = (const float*)d_in[9];
    const float* W2n  = (const float*)d_in[10];
    const float* b2   = (const float*)d_in[11];
    const float* Wfc  = (const float*)d_in[12];
    const float* bfc  = (const float*)d_in[13];
    float* out = (float*)d_out;

    float *U, *sbuf;
    __nv_bfloat16 *CTh, *CTl;
    cudaGetSymbolAddress((void**)&U,    g_U);
    cudaGetSymbolAddress((void**)&sbuf, g_s);
    cudaGetSymbolAddress((void**)&CTh,  g_CTh);
    cudaGetSymbolAddress((void**)&CTl,  g_CTl);

    const int TB = 256;
    int nblk_n = (NN + TB - 1) / TB;
    int nblk_e = (NE + TB - 1) / TB;
    int ntiles = (NN + 1023) / 1024;

    size_t smem_bytes = (size_t)SM_HALVES * sizeof(__nv_bfloat16);
    cudaFuncSetAttribute(k_wgemm, cudaFuncAttributeMaxDynamicSharedMemorySize,
                         (int)smem_bytes);

    cudaStream_t s2;
    cudaStreamCreateWithFlags(&s2, cudaStreamNonBlocking);
    cudaEvent_t eFork, eHi, eJoin;
    cudaEventCreateWithFlags(&eFork, cudaEventDisableTiming);
    cudaEventCreateWithFlags(&eHi,   cudaEventDisableTiming);
    cudaEventCreateWithFlags(&eJoin, cudaEventDisableTiming);

    cudaEventRecord(eFork, 0);
    cudaStreamWaitEvent(s2, eFork, 0);

    int gemm_grid = (NN + 63) / 64;

    // ---- chain B (s2): precompute -> gemm hi half -> gemm lo half -> rvec ----
    k_preA<<<(2 * 16384 + TB - 1) / TB, TB, 0, s2>>>(W2s, W2n, Wfc);
    k_preB<<<(3 * 16384 + TB - 1) / TB, TB, 0, s2>>>(W1s, W1n);
    k_preC<<<(4 * 8192 + TB - 1) / TB, TB, 0, s2>>>(W0s, W0n);
    // hi half: output cols 128..255 (u2, u3) — uses CT rows 128..255
    k_wgemm<<<gemm_grid, 256, smem_bytes, s2>>>(x, CTh + 128 * 128, CTl + 128 * 128,
                                                U, NN, 128);
    cudaEventRecord(eHi, s2);
    // lo half: output cols 0..127 (u0, u1)
    k_wgemm<<<gemm_grid, 256, smem_bytes, s2>>>(x, CTh, CTl, U, NN, 0);
    k_rvec<<<24, 256, 0, s2>>>(b0, b1, b2, bfc, Wfc);
    cudaEventRecord(eJoin, s2);

    // ---- chain A (default stream): CSR build ----
    k_zero_counts<<<nblk_n, TB>>>();
    k_count<<<nblk_e, TB>>>(edst);
    k_scan_tiles<<<ntiles, 1024>>>();
    k_scan_sums<<<1, 64>>>(ntiles);
    k_scan_fix<<<nblk_n, TB>>>();
    k_fill<<<nblk_e, TB>>>(esrc, edst);

    // ---- gathers: u chunks are contiguous NN x 64 arrays ----
    const float4* u0 = (const float4*)U;
    const float4* u1 = (const float4*)(U + (size_t)1 * NN * 64);
    const float4* u2 = (const float4*)(U + (size_t)2 * NN * 64);
    const float4* u3 = (const float4*)(U + (size_t)3 * NN * 64);
    float4* s2buf = (float4*)sbuf;
    float4* s1buf = (float4*)(sbuf + (size_t)NN * 64);
    int gblk = (NN * 16 + TB - 1) / TB;

    cudaStreamWaitEvent(0, eHi, 0);          // need u2, u3 + CSR
    k_gather64<<<gblk, TB>>>(u3, u2, s2buf, 1);
    cudaStreamWaitEvent(0, eJoin, 0);        // need u1, u0, r-vectors
    k_gather64<<<gblk, TB>>>(s2buf, u1, s1buf, 0);
    k_gather64<<<gblk, TB>>>(s1buf, u0, (float4*)out, 2);
}

// round 10
// speedup vs baseline: 1.1272x; 1.1272x over previous
#include <cuda_runtime.h>
#include <cuda_bf16.h>
#include <math.h>
#include <cstdint>

#define NN 50000
#define NE 800000
#define INF 128
#define HID 256
#define NCLS 64

// ---------------- device scratch ----------------
__device__ int   g_deg[NN];
__device__ int   g_cursor[NN];
__device__ int   g_off[NN + 1];
__device__ int   g_csr[NE];
__device__ float g_invdeg[NN];
__device__ int   g_tsum[64];
// U stored as 4 contiguous chunks u0,u1,u2,u3; chunk c = g_U + c*NN*64
__device__ __align__(16) float g_U[(size_t)4 * NN * 64];
__device__ __align__(16) float g_s[(size_t)2 * NN * 64];   // s2, s1
// g_pre layout: Us=0, Un=16384, Q0=32768, Q1=49152, Q2=65536
__device__ __align__(16) float g_pre[5 * 256 * 64];
__device__ __align__(16) __nv_bfloat16 g_CTh[256 * 128];   // Cbig^T hi [n][k]
__device__ __align__(16) __nv_bfloat16 g_CTl[256 * 128];   // Cbig^T lo
__device__ float g_r[3 * 64];
__device__ float g_e1[NN];
__device__ float g_e2[NN];

// ---------------- CSR build ----------------
__global__ void k_zero_counts() {
    int i = blockIdx.x * blockDim.x + threadIdx.x;
    if (i < NN) { g_deg[i] = 0; g_cursor[i] = 0; }
}

__global__ void k_count(const int* __restrict__ dst) {
    int e = blockIdx.x * blockDim.x + threadIdx.x;
    if (e < NE) atomicAdd(&g_deg[dst[e]], 1);
}

__global__ void k_scan_tiles() {
    __shared__ int sh[1024];
    int t = threadIdx.x;
    int i = blockIdx.x * 1024 + t;
    int v = (i < NN) ? g_deg[i] : 0;
    sh[t] = v;
    __syncthreads();
    for (int d = 1; d < 1024; d <<= 1) {
        int x = 0;
        if (t >= d) x = sh[t - d];
        __syncthreads();
        sh[t] += x;
        __syncthreads();
    }
    if (i < NN) g_off[i] = sh[t] - v;
    if (t == 1023) g_tsum[blockIdx.x] = sh[t];
}

__global__ void k_scan_sums(int ntiles) {
    __shared__ int sh[64];
    int t = threadIdx.x;
    int v = (t < ntiles) ? g_tsum[t] : 0;
    sh[t] = v;
    __syncthreads();
    for (int d = 1; d < 64; d <<= 1) {
        int x = 0;
        if (t >= d) x = sh[t - d];
        __syncthreads();
        sh[t] += x;
        __syncthreads();
    }
    if (t < ntiles) g_tsum[t] = sh[t] - v;
}

__global__ void k_scan_fix() {
    int i = blockIdx.x * blockDim.x + threadIdx.x;
    if (i < NN) {
        g_off[i] += g_tsum[i >> 10];
        int d = g_deg[i];
        g_invdeg[i] = 1.0f / fmaxf((float)d, 1.0f);
        g_e1[i] = (d > 0) ? 1.0f : 0.0f;
    }
    if (i == 0) g_off[NN] = NE;
}

__global__ void k_fill(const int* __restrict__ src, const int* __restrict__ dst) {
    int e = blockIdx.x * blockDim.x + threadIdx.x;
    if (e < NE) {
        int d = dst[e];
        int pos = g_off[d] + atomicAdd(&g_cursor[d], 1);
        g_csr[pos] = src[e];
    }
}

// ---------------- fused precompute stages ----------------
__global__ void k_preA(const float* __restrict__ W2s, const float* __restrict__ W2n,
                       const float* __restrict__ Wfc) {
    int idx = blockIdx.x * blockDim.x + threadIdx.x;
    if (idx >= 2 * 16384) return;
    int which = idx >> 14;
    int j = idx & 16383;
    int r = j >> 6, c = j & 63;
    const float* A = which ? W2n : W2s;
    float acc = 0.f;
    #pragma unroll 8
    for (int k = 0; k < 256; ++k) acc += A[r * 256 + k] * Wfc[k * 64 + c];
    g_pre[which * 16384 + j] = acc;
}

__global__ void k_preB(const float* __restrict__ W1s, const float* __restrict__ W1n) {
    int idx = blockIdx.x * blockDim.x + threadIdx.x;
    if (idx >= 3 * 16384) return;
    int which = idx / 16384;
    int j = idx % 16384;
    int r = j >> 6, c = j & 63;
    const float* Us = g_pre;
    const float* Un = g_pre + 16384;
    float acc = 0.f;
    if (which == 0) {
        #pragma unroll 8
        for (int k = 0; k < 256; ++k) acc += W1s[r * 256 + k] * Us[k * 64 + c];
    } else if (which == 1) {
        #pragma unroll 8
        for (int k = 0; k < 256; ++k)
            acc += W1n[r * 256 + k] * Us[k * 64 + c] + W1s[r * 256 + k] * Un[k * 64 + c];
    } else {
        #pragma unroll 8
        for (int k = 0; k < 256; ++k) acc += W1n[r * 256 + k] * Un[k * 64 + c];
    }
    g_pre[32768 + which * 16384 + j] = acc;
}

__global__ void k_preC(const float* __restrict__ W0s, const float* __restrict__ W0n) {
    int idx = blockIdx.x * blockDim.x + threadIdx.x;
    if (idx >= 4 * 8192) return;
    int chunk = idx >> 13;
    int j = idx & 8191;
    int r = j >> 6, c = j & 63;
    const float* Q0 = g_pre + 32768;
    const float* Q1 = g_pre + 49152;
    const float* Q2 = g_pre + 65536;
    float acc = 0.f;
    if (chunk == 0) {
        #pragma unroll 8
        for (int k = 0; k < 256; ++k) acc += W0s[r * 256 + k] * Q0[k * 64 + c];
    } else if (chunk == 1) {
        #pragma unroll 8
        for (int k = 0; k < 256; ++k)
            acc += W0n[r * 256 + k] * Q0[k * 64 + c] + W0s[r * 256 + k] * Q1[k * 64 + c];
    } else if (chunk == 2) {
        #pragma unroll 8
        for (int k = 0; k < 256; ++k)
            acc += W0n[r * 256 + k] * Q1[k * 64 + c] + W0s[r * 256 + k] * Q2[k * 64 + c];
    } else {
        #pragma unroll 8
        for (int k = 0; k < 256; ++k) acc += W0n[r * 256 + k] * Q2[k * 64 + c];
    }
    __nv_bfloat16 h = __float2bfloat16(acc);
    g_CTh[chunk * 8192 + c * 128 + r] = h;
    g_CTl[chunk * 8192 + c * 128 + r] = __float2bfloat16(acc - __bfloat162float(h));
}

// warp-parallel rvec: one warp per output element (192 outputs)
__global__ void k_rvec(const float* __restrict__ b0, const float* __restrict__ b1,
                       const float* __restrict__ b2, const float* __restrict__ bfc,
                       const float* __restrict__ Wfc) {
    const float* Us = g_pre;
    const float* Un = g_pre + 16384;
    const float* Q0 = g_pre + 32768;
    const float* Q1 = g_pre + 49152;
    const float* Q2 = g_pre + 65536;
    int gw = (blockIdx.x * blockDim.x + threadIdx.x) >> 5;
    int lane = threadIdx.x & 31;
    if (gw >= 192) return;
    int which = gw / 64, c = gw % 64;
    float acc = 0.f;
    if (which == 0) {
        #pragma unroll
        for (int k = lane; k < 256; k += 32)
            acc += b0[k] * Q0[k * 64 + c] + b1[k] * Us[k * 64 + c] + b2[k] * Wfc[k * 64 + c];
    } else if (which == 1) {
        #pragma unroll
        for (int k = lane; k < 256; k += 32)
            acc += b0[k] * Q1[k * 64 + c] + b1[k] * Un[k * 64 + c];
    } else {
        #pragma unroll
        for (int k = lane; k < 256; k += 32)
            acc += b0[k] * Q2[k * 64 + c];
    }
    #pragma unroll
    for (int o = 16; o > 0; o >>= 1)
        acc += __shfl_xor_sync(0xFFFFFFFFu, acc, o);
    if (lane == 0) {
        if (which == 0) acc += bfc[c];
        g_r[gw] = acc;
    }
}

// ---------------- 64-dim mean gather, x8 unrolled, fused add ----------------
// all row strides are 16 float4s. mode: 0 plain ; 1 also g_e2 ; 2 add bias combo
__global__ void k_gather64(const float4* __restrict__ src,
                           const float4* __restrict__ add,
                           float4* __restrict__ out, int mode) {
    int gtid = blockIdx.x * blockDim.x + threadIdx.x;
    int node = gtid >> 4;
    int c = gtid & 15;
    if (node >= NN) return;
    int s = g_off[node], e = g_off[node + 1];
    float4 a0 = make_float4(0.f, 0.f, 0.f, 0.f);
    float4 a1 = make_float4(0.f, 0.f, 0.f, 0.f);
    float4 a2 = make_float4(0.f, 0.f, 0.f, 0.f);
    float4 a3 = make_float4(0.f, 0.f, 0.f, 0.f);
    float ecnt = 0.f;
    int idx = s;
    for (; idx + 8 <= e; idx += 8) {
        int n[8];
        #pragma unroll
        for (int j = 0; j < 8; ++j) n[j] = g_csr[idx + j];
        float4 v[8];
        #pragma unroll
        for (int j = 0; j < 8; ++j) v[j] = src[(size_t)n[j] * 16 + c];
        if (mode == 1 && c == 0) {
            #pragma unroll
            for (int j = 0; j < 8; ++j) ecnt += (g_deg[n[j]] > 0) ? 1.f : 0.f;
        }
        a0.x += v[0].x; a0.y += v[0].y; a0.z += v[0].z; a0.w += v[0].w;
        a1.x += v[1].x; a1.y += v[1].y; a1.z += v[1].z; a1.w += v[1].w;
        a2.x += v[2].x; a2.y += v[2].y; a2.z += v[2].z; a2.w += v[2].w;
        a3.x += v[3].x; a3.y += v[3].y; a3.z += v[3].z; a3.w += v[3].w;
        a0.x += v[4].x; a0.y += v[4].y; a0.z += v[4].z; a0.w += v[4].w;
        a1.x += v[5].x; a1.y += v[5].y; a1.z += v[5].z; a1.w += v[5].w;
        a2.x += v[6].x; a2.y += v[6].y; a2.z += v[6].z; a2.w += v[6].w;
        a3.x += v[7].x; a3.y += v[7].y; a3.z += v[7].z; a3.w += v[7].w;
    }
    for (; idx + 2 <= e; idx += 2) {
        int n0 = g_csr[idx], n1 = g_csr[idx + 1];
        float4 v0 = src[(size_t)n0 * 16 + c];
        float4 v1 = src[(size_t)n1 * 16 + c];
        if (mode == 1 && c == 0)
            ecnt += ((g_deg[n0] > 0) ? 1.f : 0.f) + ((g_deg[n1] > 0) ? 1.f : 0.f);
        a0.x += v0.x; a0.y += v0.y; a0.z += v0.z; a0.w += v0.w;
        a1.x += v1.x; a1.y += v1.y; a1.z += v1.z; a1.w += v1.w;
    }
    if (idx < e) {
        int sn = g_csr[idx];
        float4 v = src[(size_t)sn * 16 + c];
        if (mode == 1 && c == 0) ecnt += (g_deg[sn] > 0) ? 1.f : 0.f;
        a0.x += v.x; a0.y += v.y; a0.z += v.z; a0.w += v.w;
    }
    a0.x += a1.x + a2.x + a3.x;
    a0.y += a1.y + a2.y + a3.y;
    a0.z += a1.z + a2.z + a3.z;
    a0.w += a1.w + a2.w + a3.w;
    float w = g_invdeg[node];
    if (mode == 1 && c == 0) g_e2[node] = ecnt * w;
    float4 r = add[(size_t)node * 16 + c];
    r.x += a0.x * w; r.y += a0.y * w; r.z += a0.z * w; r.w += a0.w * w;
    if (mode == 2) {
        float a = g_e1[node], b = g_e2[node];
        const float4* r0 = (const float4*)g_r;
        const float4* r1 = r0 + 16;
        const float4* r2 = r0 + 32;
        float4 v0 = r0[c], v1 = r1[c], v2 = r2[c];
        r.x += v0.x + a * v1.x + b * v2.x;
        r.y += v0.y + a * v1.y + b * v2.y;
        r.z += v0.z + a * v1.z + b * v2.z;
        r.w += v0.w + a * v1.w + b * v2.w;
    }
    out[(size_t)node * 16 + c] = r;
}

// ---------------- mma.sync bf16 split-precision GEMM, ldmatrix loads ----------------
// Full-width: BM=128 x BN=128, grid (2, 391); colbase = blockIdx.x * 128.
#define LDK 136
#define SM_AH 0
#define SM_AL (128 * LDK)
#define SM_BH (2 * 128 * LDK)
#define SM_BL (3 * 128 * LDK)
#define SM_HALVES (4 * 128 * LDK)

#define MMA16816(c, a, b0_, b1_) \
    asm volatile("mma.sync.aligned.m16n8k16.row.col.f32.bf16.bf16.f32 " \
        "{%0,%1,%2,%3}, {%4,%5,%6,%7}, {%8,%9}, {%0,%1,%2,%3};" \
        : "+f"((c)[0]), "+f"((c)[1]), "+f"((c)[2]), "+f"((c)[3]) \
        : "r"((a)[0]), "r"((a)[1]), "r"((a)[2]), "r"((a)[3]), \
          "r"(b0_), "r"(b1_))

#define LDSM4(r0, r1, r2, r3, addr) \
    asm volatile("ldmatrix.sync.aligned.m8n8.x4.shared.b16 {%0,%1,%2,%3}, [%4];" \
        : "=r"(r0), "=r"(r1), "=r"(r2), "=r"(r3) : "r"(addr))

__global__ __launch_bounds__(256, 1)
void k_wgemm(const float* __restrict__ x, const __nv_bfloat16* __restrict__ CTh,
             const __nv_bfloat16* __restrict__ CTl, float* __restrict__ U, int M) {
    extern __shared__ __nv_bfloat16 sm[];
    __nv_bfloat16* Ah = sm + SM_AH;
    __nv_bfloat16* Al = sm + SM_AL;
    __nv_bfloat16* Bh = sm + SM_BH;
    __nv_bfloat16* Bl = sm + SM_BL;

    const int tid = threadIdx.x;
    const int bm = blockIdx.y * 128;
    const int colbase = blockIdx.x * 128;
    const __nv_bfloat16* cth = CTh + (size_t)colbase * 128;
    const __nv_bfloat16* ctl = CTl + (size_t)colbase * 128;

    // ---- stage A: rows bm..bm+127 of x -> bf16 hi/lo ----
    {
        int r = tid >> 1;
        int half = tid & 1;
        int grow = bm + r;
        const float4* xr = (const float4*)(x + (size_t)grow * 128 + half * 64);
        __nv_bfloat16* ah = Ah + r * LDK + half * 64;
        __nv_bfloat16* al = Al + r * LDK + half * 64;
        #pragma unroll
        for (int j = 0; j < 8; ++j) {
            float f[8];
            if (grow < M) {
                float4 v0 = xr[2 * j], v1 = xr[2 * j + 1];
                f[0] = v0.x; f[1] = v0.y; f[2] = v0.z; f[3] = v0.w;
                f[4] = v1.x; f[5] = v1.y; f[6] = v1.z; f[7] = v1.w;
            } else {
                #pragma unroll
                for (int e = 0; e < 8; ++e) f[e] = 0.f;
            }
            uint32_t hp[4], lp[4];
            #pragma unroll
            for (int e = 0; e < 4; ++e) {
                __nv_bfloat16 h0 = __float2bfloat16(f[2 * e]);
                __nv_bfloat16 h1 = __float2bfloat16(f[2 * e + 1]);
                float l0 = f[2 * e]     - __bfloat162float(h0);
                float l1 = f[2 * e + 1] - __bfloat162float(h1);
                __nv_bfloat162 hh = __halves2bfloat162(h0, h1);
                __nv_bfloat162 lv = __halves2bfloat162(__float2bfloat16(l0),
                                                       __float2bfloat16(l1));
                hp[e] = *(uint32_t*)&hh;
                lp[e] = *(uint32_t*)&lv;
            }
            *(uint4*)(ah + 8 * j) = make_uint4(hp[0], hp[1], hp[2], hp[3]);
            *(uint4*)(al + 8 * j) = make_uint4(lp[0], lp[1], lp[2], lp[3]);
        }
    }
    // ---- stage B: 128 CT rows of this column half ----
    {
        int r = tid >> 1;
        int half = tid & 1;
        const uint4* sh = (const uint4*)(cth + (size_t)r * 128 + half * 64);
        const uint4* sl = (const uint4*)(ctl + (size_t)r * 128 + half * 64);
        uint4* dh = (uint4*)(Bh + r * LDK + half * 64);
        uint4* dl = (uint4*)(Bl + r * LDK + half * 64);
        #pragma unroll
        for (int j = 0; j < 8; ++j) { dh[j] = sh[j]; dl[j] = sl[j]; }
    }
    __syncthreads();

    const int w = tid >> 5, lane = tid & 31;
    const int wm = (w >> 2) * 64;          // 2 m-groups of 64 rows
    const int wn = (w & 3) * 32;           // 4 n-groups of 32 cols
    const int lr = lane >> 2;
    const int lc = (lane & 3) * 2;
    const int g  = lane >> 3, gl = lane & 7;
    const int a_r = (g & 1) * 8 + gl;      // A: matrices [rows, rows+8] x [k, k+8]
    const int a_c = (g >> 1) * 8;
    const int b_r = (g >> 1) * 8 + gl;     // B: matrices [fn, fn+1] x [k, k+8]
    const int b_c = (g & 1) * 8;

    float acc[4][4][4];
    #pragma unroll
    for (int i = 0; i < 4; ++i)
        #pragma unroll
        for (int j = 0; j < 4; ++j)
            #pragma unroll
            for (int e = 0; e < 4; ++e) acc[i][j][e] = 0.f;

    #pragma unroll
    for (int pass = 0; pass < 3; ++pass) {
        const __nv_bfloat16* As = (pass == 2) ? Al : Ah;
        const __nv_bfloat16* Bs = (pass == 1) ? Bl : Bh;
        #pragma unroll
        for (int ks = 0; ks < 8; ++ks) {
            int kb = ks * 16;
            uint32_t a[4][4];
            #pragma unroll
            for (int fm = 0; fm < 4; ++fm) {
                uint32_t addr = (uint32_t)__cvta_generic_to_shared(
                    &As[(wm + fm * 16 + a_r) * LDK + kb + a_c]);
                LDSM4(a[fm][0], a[fm][1], a[fm][2], a[fm][3], addr);
            }
            uint32_t b[4][2];
            #pragma unroll
            for (int p = 0; p < 2; ++p) {
                uint32_t addr = (uint32_t)__cvta_generic_to_shared(
                    &Bs[(wn + p * 16 + b_r) * LDK + kb + b_c]);
                LDSM4(b[2 * p][0], b[2 * p][1], b[2 * p + 1][0], b[2 * p + 1][1], addr);
            }
            #pragma unroll
            for (int fn = 0; fn < 4; ++fn)
                #pragma unroll
                for (int fm = 0; fm < 4; ++fm)
                    MMA16816(acc[fm][fn], a[fm], b[fn][0], b[fn][1]);
        }
    }

    // ---- epilogue into chunked U ----
    #pragma unroll
    for (int fm = 0; fm < 4; ++fm) {
        int r0 = bm + wm + fm * 16 + lr;
        int r1 = r0 + 8;
        #pragma unroll
        for (int fn = 0; fn < 4; ++fn) {
            int col = colbase + wn + fn * 8 + lc;
            int chunk = col >> 6, off = col & 63;
            float* dst = U + (size_t)chunk * NN * 64 + off;
            if (r0 < M)
                *(float2*)(dst + (size_t)r0 * 64) =
                    make_float2(acc[fm][fn][0], acc[fm][fn][1]);
            if (r1 < M)
                *(float2*)(dst + (size_t)r1 * 64) =
                    make_float2(acc[fm][fn][2], acc[fm][fn][3]);
        }
    }
}

// ---------------- launch ----------------
extern "C" void kernel_launch(void* const* d_in, const int* in_sizes, int n_in,
                              void* d_out, int out_size) {
    const float* x    = (const float*)d_in[0];
    const int*   esrc = (const int*)d_in[1];
    const int*   edst = (const int*)d_in[2];
    const float* W0s  = (const float*)d_in[3];
    const float* W0n  = (const float*)d_in[4];
    const float* b0   = (const float*)d_in[5];
    const float* W1s  = (const float*)d_in[6];
    const float* W1n  = (const float*)d_in[7];
    const float* b1   = (const float*)d_in[8];
    const float* W2s  = (const float*)d_in[9];
    const float* W2n  = (const float*)d_in[10];
    const float* b2   = (const float*)d_in[11];
    const float* Wfc  = (const float*)d_in[12];
    const float* bfc  = (const float*)d_in[13];
    float* out = (float*)d_out;

    float *U, *sbuf;
    __nv_bfloat16 *CTh, *CTl;
    cudaGetSymbolAddress((void**)&U,    g_U);
    cudaGetSymbolAddress((void**)&sbuf, g_s);
    cudaGetSymbolAddress((void**)&CTh,  g_CTh);
    cudaGetSymbolAddress((void**)&CTl,  g_CTl);

    const int TB = 256;
    int nblk_n = (NN + TB - 1) / TB;
    int nblk_e = (NE + TB - 1) / TB;
    int ntiles = (NN + 1023) / 1024;

    size_t smem_bytes = (size_t)SM_HALVES * sizeof(__nv_bfloat16);
    cudaFuncSetAttribute(k_wgemm, cudaFuncAttributeMaxDynamicSharedMemorySize,
                         (int)smem_bytes);

    cudaStream_t s2;
    cudaStreamCreateWithFlags(&s2, cudaStreamNonBlocking);
    cudaEvent_t eFork, eJoin;
    cudaEventCreateWithFlags(&eFork, cudaEventDisableTiming);
    cudaEventCreateWithFlags(&eJoin, cudaEventDisableTiming);

    cudaEventRecord(eFork, 0);
    cudaStreamWaitEvent(s2, eFork, 0);

    // ---- chain B (s2): precompute -> rvec -> full GEMM ----
    k_preA<<<(2 * 16384 + TB - 1) / TB, TB, 0, s2>>>(W2s, W2n, Wfc);
    k_preB<<<(3 * 16384 + TB - 1) / TB, TB, 0, s2>>>(W1s, W1n);
    k_preC<<<(4 * 8192 + TB - 1) / TB, TB, 0, s2>>>(W0s, W0n);
    k_rvec<<<24, 256, 0, s2>>>(b0, b1, b2, bfc, Wfc);
    {
        dim3 gG(2, (NN + 127) / 128);
        k_wgemm<<<gG, 256, smem_bytes, s2>>>(x, CTh, CTl, U, NN);
    }
    cudaEventRecord(eJoin, s2);

    // ---- chain A (default stream): CSR build ----
    k_zero_counts<<<nblk_n, TB>>>();
    k_count<<<nblk_e, TB>>>(edst);
    k_scan_tiles<<<ntiles, 1024>>>();
    k_scan_sums<<<1, 64>>>(ntiles);
    k_scan_fix<<<nblk_n, TB>>>();
    k_fill<<<nblk_e, TB>>>(esrc, edst);

    // join
    cudaStreamWaitEvent(0, eJoin, 0);

    // ---- Horner aggregation over chunked U ----
    const float4* u0 = (const float4*)U;
    const float4* u1 = (const float4*)(U + (size_t)1 * NN * 64);
    const float4* u2 = (const float4*)(U + (size_t)2 * NN * 64);
    const float4* u3 = (const float4*)(U + (size_t)3 * NN * 64);
    float4* s2buf = (float4*)sbuf;
    float4* s1buf = (float4*)(sbuf + (size_t)NN * 64);
    int gblk = (NN * 16 + TB - 1) / TB;
    k_gather64<<<gblk, TB>>>(u3, u2, s2buf, 1);
    k_gather64<<<gblk, TB>>>(s2buf, u1, s1buf, 0);
    k_gather64<<<gblk, TB>>>(s1buf, u0, (float4*)out, 2);
}